// round 6
// baseline (speedup 1.0000x reference)
#include <cuda_runtime.h>
#include <cstdint>

#define N_NODES 50000
#define N_EDGES 800000
#define N_GRAPHS 64
#define DD 64
#define N_GIN 4
#define N_PRED 5

// ---------------- scratch (device globals; no allocation) ----------------
__device__ float d_z[N_NODES * DD];            // GINConv output (h + agg)
__device__ float d_y[N_NODES * DD];            // MLP output (pre-BN)
__device__ unsigned d_pxmax[N_GRAPHS * DD];    // encoded max of raw x
__device__ unsigned d_pymax[N_GIN][N_GRAPHS * DD];  // encoded max of y
__device__ unsigned d_pyneg[N_GIN][N_GRAPHS * DD];  // encoded max of -y
__device__ float d_stats[N_GIN * 128];         // per-layer col sums / sumsq
__device__ int d_deg[N_NODES];                 // degree -> cursor -> row end
__device__ int d_off[N_NODES];                 // CSR row start
__device__ int d_csr[N_EDGES];                 // src ids grouped by dst

// monotone float<->uint encoding for atomicMax on floats
__device__ __forceinline__ unsigned enc_f(float x) {
    unsigned u = __float_as_uint(x);
    return (u & 0x80000000u) ? ~u : (u | 0x80000000u);
}
__device__ __forceinline__ float dec_f(unsigned u) {
    u = (u & 0x80000000u) ? (u & 0x7fffffffu) : ~u;
    return __uint_as_float(u);
}

// ---------------- zero everything ----------------------------------------
__global__ void zero_kernel() {
    int i = blockIdx.x * 256 + threadIdx.x;
    if (i < N_NODES) d_deg[i] = 0;
    if (i < N_GRAPHS * DD) d_pxmax[i] = 0u;
    if (i < N_GIN * N_GRAPHS * DD) {
        ((unsigned*)d_pymax)[i] = 0u;
        ((unsigned*)d_pyneg)[i] = 0u;
    }
    if (i < N_GIN * 128) d_stats[i] = 0.f;
}

// ---------------- histogram of dst ---------------------------------------
__global__ void hist_kernel(const int* __restrict__ dst) {
    int e = blockIdx.x * 256 + threadIdx.x;   // 3125 blocks exactly
    atomicAdd(&d_deg[dst[e]], 1);
}

// ------- single-block exclusive scan, thread-coarsened (49 elem/thr) -----
__global__ void scan_kernel() {
    const int C = 49;   // 1024 * 49 = 50176 >= N_NODES
    __shared__ int wsum[32];
    int tid = threadIdx.x, lane = tid & 31, wid = tid >> 5;
    int base = tid * C;
    int s = 0;
    for (int k = 0; k < C; k++) {
        int i = base + k;
        if (i < N_NODES) s += d_deg[i];
    }
    int x = s;
#pragma unroll
    for (int o = 1; o < 32; o <<= 1) {
        int y = __shfl_up_sync(0xffffffffu, x, o);
        if (lane >= o) x += y;
    }
    if (lane == 31) wsum[wid] = x;
    __syncthreads();
    if (wid == 0) {
        int w = wsum[lane];
#pragma unroll
        for (int o = 1; o < 32; o <<= 1) {
            int y = __shfl_up_sync(0xffffffffu, w, o);
            if (lane >= o) w += y;
        }
        wsum[lane] = w;
    }
    __syncthreads();
    int excl = x - s + (wid ? wsum[wid - 1] : 0);
    for (int k = 0; k < C; k++) {
        int i = base + k;
        if (i < N_NODES) {
            int v = d_deg[i];
            d_off[i] = excl;
            d_deg[i] = excl;   // becomes fill cursor
            excl += v;
        }
    }
}

// ---------------- permute edges into CSR ----------------------------------
// after this, d_deg[n] == row end
__global__ void permute_kernel(const int* __restrict__ src,
                               const int* __restrict__ dst) {
    int e = blockIdx.x * 256 + threadIdx.x;   // 3125 blocks exactly
    int d = dst[e];
    int pos = atomicAdd(&d_deg[d], 1);
    d_csr[pos] = src[e];
}

// ------- gather with on-the-fly BN+PReLU of previous layer ---------------
// z[n] = h(n) + sum_{j->n} h(src),  h(r) = prelu(scale*y(r)+bias) (l>0) or x
__global__ void gather_kernel(const float* __restrict__ x,
                              const float* __restrict__ gamma,
                              const float* __restrict__ beta,
                              const float* __restrict__ alpha_p, int layer) {
    int t = blockIdx.x * 256 + threadIdx.x;   // 800000 threads exactly
    int node = t >> 4;
    int c = (t & 15) << 2;

    float s0 = 1.f, s1 = 1.f, s2 = 1.f, s3 = 1.f;
    float o0 = 0.f, o1 = 0.f, o2 = 0.f, o3 = 0.f;
    float al = 0.f;
    const float* h = x;
    if (layer) {
        h = (const float*)d_y;
        al = __ldg(alpha_p);
        int so = (layer - 1) * 128;
        int go = (layer - 1) * 64;
#pragma unroll
        for (int j = 0; j < 4; j++) {
            float mean = d_stats[so + c + j] * (1.f / N_NODES);
            float msq = d_stats[so + 64 + c + j] * (1.f / N_NODES);
            float rstd = rsqrtf(msq - mean * mean + 1e-5f);
            float sc = rstd * __ldg(&gamma[go + c + j]);
            float bs = __ldg(&beta[go + c + j]) - mean * sc;
            if (j == 0) { s0 = sc; o0 = bs; }
            else if (j == 1) { s1 = sc; o1 = bs; }
            else if (j == 2) { s2 = sc; o2 = bs; }
            else { s3 = sc; o3 = bs; }
        }
    }

#define XFORM(v)                                                     \
    if (layer) {                                                     \
        v.x = fmaf(v.x, s0, o0); v.x = fmaxf(v.x, 0.f) + al * fminf(v.x, 0.f); \
        v.y = fmaf(v.y, s1, o1); v.y = fmaxf(v.y, 0.f) + al * fminf(v.y, 0.f); \
        v.z = fmaf(v.z, s2, o2); v.z = fmaxf(v.z, 0.f) + al * fminf(v.z, 0.f); \
        v.w = fmaf(v.w, s3, o3); v.w = fmaxf(v.w, 0.f) + al * fminf(v.w, 0.f); \
    }

    int beg = d_off[node];
    int end = d_deg[node];
    float4 a = *(const float4*)(h + (size_t)node * DD + c);
    XFORM(a);
    for (int j = beg; j < end; j++) {
        int s = __ldg(&d_csr[j]);
        float4 v = *(const float4*)(h + (size_t)s * DD + c);
        XFORM(v);
        a.x += v.x; a.y += v.y; a.z += v.z; a.w += v.w;
    }
    *(float4*)(d_z + (size_t)node * DD + c) = a;
#undef XFORM
}

// ---------------- fused MLP + BN stats + y max/min pooling ----------------
// BM=128 rows/block, 128 threads, 8x8 register tiles, FFMA2 inner loops.
__global__ void __launch_bounds__(128) mlp_kernel(
        int layer,
        const float* __restrict__ W1, const float* __restrict__ b1,
        const float* __restrict__ W2, const float* __restrict__ b2) {
    extern __shared__ float smem[];
    float (*zs)[65] = (float(*)[65])smem;                    // [128][65]
    float (*ws)[64] = (float(*)[64])(smem + 128 * 65);       // [64][64]
    __shared__ unsigned pmx[2][64], pmn[2][64];

    int tid = threadIdx.x;
    int rbase = blockIdx.x * 128;

    pmx[tid >> 6][tid & 63] = 0u;
    pmn[tid >> 6][tid & 63] = 0u;

    for (int i = tid; i < 4096; i += 128) ws[i >> 6][i & 63] = W1[i];
    for (int idx = tid; idx < 128 * 16; idx += 128) {
        int r = idx >> 4, c4 = (idx & 15) << 2;
        int gr = rbase + r;
        float4 v = (gr < N_NODES)
                 ? *(const float4*)(d_z + (size_t)gr * DD + c4)
                 : make_float4(0.f, 0.f, 0.f, 0.f);
        zs[r][c4 + 0] = v.x; zs[r][c4 + 1] = v.y;
        zs[r][c4 + 2] = v.z; zs[r][c4 + 3] = v.w;
    }
    __syncthreads();

    int tx = tid & 7, ty = tid >> 3;
    int c0 = tx << 3, r0 = ty << 3;

    unsigned long long acc[8][4];
#pragma unroll
    for (int i = 0; i < 8; i++)
#pragma unroll
        for (int p = 0; p < 4; p++) acc[i][p] = 0ull;

#pragma unroll 4
    for (int k = 0; k < 64; k++) {
        unsigned long long bb[4];
#pragma unroll
        for (int p = 0; p < 4; p++)
            bb[p] = *(const unsigned long long*)&ws[k][c0 + 2 * p];
#pragma unroll
        for (int i = 0; i < 8; i++) {
            unsigned ai = __float_as_uint(zs[r0 + i][k]);
            unsigned long long aa;
            asm("mov.b64 %0, {%1, %1};" : "=l"(aa) : "r"(ai));
#pragma unroll
            for (int p = 0; p < 4; p++)
                asm("fma.rn.f32x2 %0, %1, %2, %0;"
                    : "+l"(acc[i][p]) : "l"(aa), "l"(bb[p]));
        }
    }
    __syncthreads();

    // bias + relu -> back into zs; load W2
#pragma unroll
    for (int i = 0; i < 8; i++) {
#pragma unroll
        for (int p = 0; p < 4; p++) {
            unsigned ulo, uhi;
            asm("mov.b64 {%0, %1}, %2;" : "=r"(ulo), "=r"(uhi) : "l"(acc[i][p]));
            float lo = __uint_as_float(ulo) + __ldg(&b1[c0 + 2 * p]);
            float hi = __uint_as_float(uhi) + __ldg(&b1[c0 + 2 * p + 1]);
            zs[r0 + i][c0 + 2 * p] = lo > 0.f ? lo : 0.f;
            zs[r0 + i][c0 + 2 * p + 1] = hi > 0.f ? hi : 0.f;
        }
    }
    for (int i = tid; i < 4096; i += 128) ws[i >> 6][i & 63] = W2[i];
    __syncthreads();

#pragma unroll
    for (int i = 0; i < 8; i++)
#pragma unroll
        for (int p = 0; p < 4; p++) acc[i][p] = 0ull;

#pragma unroll 4
    for (int k = 0; k < 64; k++) {
        unsigned long long bb[4];
#pragma unroll
        for (int p = 0; p < 4; p++)
            bb[p] = *(const unsigned long long*)&ws[k][c0 + 2 * p];
#pragma unroll
        for (int i = 0; i < 8; i++) {
            unsigned ai = __float_as_uint(zs[r0 + i][k]);
            unsigned long long aa;
            asm("mov.b64 %0, {%1, %1};" : "=l"(aa) : "r"(ai));
#pragma unroll
            for (int p = 0; p < 4; p++)
                asm("fma.rn.f32x2 %0, %1, %2, %0;"
                    : "+l"(acc[i][p]) : "l"(aa), "l"(bb[p]));
        }
    }

    // ---- epilogue: bias, write y, stats, max/min pooling ----
    float bb2[8];
#pragma unroll
    for (int j = 0; j < 8; j++) bb2[j] = __ldg(&b2[c0 + j]);

    int gfirst = (int)((long long)rbase * 64 / N_NODES);
    int rowsplit = (int)(((long long)(gfirst + 1) * N_NODES + 63) >> 6);
    int r0g = rbase + r0;
    int nvalid = N_NODES - r0g;
    if (nvalid > 8) nvalid = 8;
    if (nvalid < 0) nvalid = 0;
    int bsp = rowsplit - r0g;
    if (bsp < 0) bsp = 0;
    if (bsp > 8) bsp = 8;

    float psum[8], psq[8], mx[8], mn[8];
#pragma unroll
    for (int j = 0; j < 8; j++) {
        psum[j] = 0.f; psq[j] = 0.f;
        mx[j] = -3.402823466e+38f; mn[j] = 3.402823466e+38f;
    }
    int curgi = (0 < bsp) ? 0 : 1;
    bool any = false;

#pragma unroll
    for (int i = 0; i < 8; i++) {
        if (i < nvalid) {
            float o[8];
#pragma unroll
            for (int p = 0; p < 4; p++) {
                unsigned ulo, uhi;
                asm("mov.b64 {%0, %1}, %2;" : "=r"(ulo), "=r"(uhi) : "l"(acc[i][p]));
                o[2 * p] = __uint_as_float(ulo) + bb2[2 * p];
                o[2 * p + 1] = __uint_as_float(uhi) + bb2[2 * p + 1];
            }
            float4* yo = (float4*)(d_y + (size_t)(r0g + i) * DD + c0);
            yo[0] = make_float4(o[0], o[1], o[2], o[3]);
            yo[1] = make_float4(o[4], o[5], o[6], o[7]);
            int gi = (i < bsp) ? 0 : 1;
            if (gi != curgi) {
                if (any) {
#pragma unroll
                    for (int j = 0; j < 8; j++) {
                        atomicMax(&pmx[curgi][c0 + j], enc_f(mx[j]));
                        atomicMax(&pmn[curgi][c0 + j], enc_f(-mn[j]));
                        mx[j] = -3.402823466e+38f; mn[j] = 3.402823466e+38f;
                    }
                }
                curgi = gi; any = false;
            }
#pragma unroll
            for (int j = 0; j < 8; j++) {
                psum[j] += o[j];
                psq[j] += o[j] * o[j];
                mx[j] = fmaxf(mx[j], o[j]);
                mn[j] = fminf(mn[j], o[j]);
            }
            any = true;
        }
    }
    if (any) {
#pragma unroll
        for (int j = 0; j < 8; j++) {
            atomicMax(&pmx[curgi][c0 + j], enc_f(mx[j]));
            atomicMax(&pmn[curgi][c0 + j], enc_f(-mn[j]));
        }
    }

    // warp-reduce stats across the 4 row-groups sharing columns
#pragma unroll
    for (int j = 0; j < 8; j++) {
        psum[j] += __shfl_xor_sync(0xffffffffu, psum[j], 8);
        psum[j] += __shfl_xor_sync(0xffffffffu, psum[j], 16);
        psq[j]  += __shfl_xor_sync(0xffffffffu, psq[j], 8);
        psq[j]  += __shfl_xor_sync(0xffffffffu, psq[j], 16);
    }
    if ((tid & 31) < 8) {
#pragma unroll
        for (int j = 0; j < 8; j++) {
            atomicAdd(&d_stats[layer * 128 + c0 + j], psum[j]);
            atomicAdd(&d_stats[layer * 128 + 64 + c0 + j], psq[j]);
        }
    }

    __syncthreads();
    // flush block pooling to global
    {
        int gi = tid >> 6, col = tid & 63;
        int lastrow = rbase + 127;
        if (lastrow >= N_NODES) lastrow = N_NODES - 1;
        int glast = (int)((long long)lastrow * 64 / N_NODES);
        if (gfirst + gi <= glast) {
            atomicMax(&d_pymax[layer][(gfirst + gi) * DD + col], pmx[gi][col]);
            atomicMax(&d_pyneg[layer][(gfirst + gi) * DD + col], pmn[gi][col]);
        }
    }
}

// ---------------- max-pool of raw input (slot 0), 1024 blocks -------------
__global__ void pool_x_kernel(const float* __restrict__ in) {
    int g = blockIdx.x >> 4, chunk = blockIdx.x & 15;
    int tid = threadIdx.x;
    int gs = (int)(((long long)g * N_NODES + 63) >> 6);
    int ge = (int)(((long long)(g + 1) * N_NODES + 63) >> 6);
    int cnt = ge - gs;
    int step = (cnt + 15) >> 4;
    int cs = gs + chunk * step;
    int ce = min(cs + step, ge);
    int col = tid & 63, rs = tid >> 6;
    float m = -3.402823466e+38f;
    for (int r = cs + rs; r < ce; r += 4)
        m = fmaxf(m, __ldg(in + (size_t)r * DD + col));
    __shared__ float red[256];
    red[tid] = m;
    __syncthreads();
    if (rs == 0 && cs < ce) {
        m = fmaxf(fmaxf(red[col], red[64 + col]),
                  fmaxf(red[128 + col], red[192 + col]));
        atomicMax(&d_pxmax[g * DD + col], enc_f(m));
    }
}

// --------- heads: finalize pooled values (BN+PReLU) + linear --------------
__global__ void head_kernel(const float* __restrict__ gamma,
                            const float* __restrict__ beta,
                            const float* __restrict__ alpha_p,
                            const float* __restrict__ pW,
                            const float* __restrict__ pb,
                            float* __restrict__ out) {
    int g = blockIdx.x, tid = threadIdx.x;   // 320 threads
    __shared__ float ps[N_PRED * DD];
    int l = tid >> 6, col = tid & 63;
    float v;
    if (l == 0) {
        v = dec_f(d_pxmax[g * DD + col]);
    } else {
        int lm = l - 1;
        float mean = d_stats[lm * 128 + col] * (1.f / N_NODES);
        float msq = d_stats[lm * 128 + 64 + col] * (1.f / N_NODES);
        float rstd = rsqrtf(msq - mean * mean + 1e-5f);
        float sc = rstd * __ldg(&gamma[lm * 64 + col]);
        float bs = __ldg(&beta[lm * 64 + col]) - mean * sc;
        float ymax = dec_f(d_pymax[lm][g * DD + col]);
        float ymin = -dec_f(d_pyneg[lm][g * DD + col]);
        float yv = (sc >= 0.f) ? ymax : ymin;   // affine+PReLU monotone in y
        float al = __ldg(alpha_p);
        v = fmaf(yv, sc, bs);
        v = fmaxf(v, 0.f) + al * fminf(v, 0.f);
    }
    ps[tid] = v;
    __syncthreads();
    float acc = __ldg(&pb[l * DD + col]);
    const float* w = pW + l * DD * DD + col;
    const float* p = ps + l * DD;
#pragma unroll 16
    for (int k = 0; k < DD; k++) acc += p[k] * __ldg(&w[k * DD]);
    out[g * (N_PRED * DD) + col * N_PRED + l] = acc;
}

// ---------------- launch --------------------------------------------------
extern "C" void kernel_launch(void* const* d_in, const int* in_sizes, int n_in,
                              void* d_out, int out_size) {
    const float* x     = (const float*)d_in[0];
    const int* ei      = (const int*)d_in[1];
    // d_in[2] = batch (contiguous; recomputed analytically)
    const float* W1    = (const float*)d_in[3];
    const float* b1    = (const float*)d_in[4];
    const float* W2    = (const float*)d_in[5];
    const float* b2    = (const float*)d_in[6];
    const float* gamma = (const float*)d_in[7];
    const float* beta  = (const float*)d_in[8];
    const float* alpha = (const float*)d_in[9];
    const float* pW    = (const float*)d_in[10];
    const float* pb    = (const float*)d_in[11];
    float* out = (float*)d_out;

    const int* src = ei;
    const int* dst = ei + N_EDGES;

    const int MLP_SMEM = (128 * 65 + 64 * 64) * 4;  // 49664 bytes
    cudaFuncSetAttribute(mlp_kernel,
                         cudaFuncAttributeMaxDynamicSharedMemorySize, MLP_SMEM);

    zero_kernel<<<(N_NODES + 255) / 256, 256>>>();
    hist_kernel<<<N_EDGES / 256, 256>>>(dst);
    scan_kernel<<<1, 1024>>>();
    permute_kernel<<<N_EDGES / 256, 256>>>(src, dst);

    pool_x_kernel<<<N_GRAPHS * 16, 256>>>(x);

    for (int l = 0; l < N_GIN; l++) {
        gather_kernel<<<(N_NODES * 16) / 256, 256>>>(x, gamma, beta, alpha, l);
        mlp_kernel<<<(N_NODES + 127) / 128, 128, MLP_SMEM>>>(
            l, W1 + l * 4096, b1 + l * 64, W2 + l * 4096, b2 + l * 64);
    }

    head_kernel<<<N_GRAPHS, 320>>>(gamma, beta, alpha, pW, pb, out);
}

// round 7
// speedup vs baseline: 1.0157x; 1.0157x over previous
#include <cuda_runtime.h>
#include <cstdint>

#define N_NODES 50000
#define N_EDGES 800000
#define N_GRAPHS 64
#define DD 64
#define N_GIN 4
#define N_PRED 5

// ---------------- scratch (device globals; no allocation) ----------------
__device__ float d_z[N_NODES * DD];          // GINConv output (h + agg)
__device__ float d_y[N_NODES * DD];          // MLP output (pre-BN)
__device__ float d_h[N_NODES * DD];          // post-BN/PReLU hidden
__device__ unsigned d_pmax[N_PRED * N_GRAPHS * DD];  // encoded max-pool
__device__ float d_stats[128];               // col sums / sumsq (per layer)
__device__ int d_deg[N_NODES];               // degree -> cursor -> row end
__device__ int d_off[N_NODES];               // CSR row start
__device__ int d_csr[N_EDGES];               // src ids grouped by dst

// monotone float<->uint encoding for atomicMax on floats
__device__ __forceinline__ unsigned enc_f(float x) {
    unsigned u = __float_as_uint(x);
    return (u & 0x80000000u) ? ~u : (u | 0x80000000u);
}
__device__ __forceinline__ float dec_f(unsigned u) {
    u = (u & 0x80000000u) ? (u & 0x7fffffffu) : ~u;
    return __uint_as_float(u);
}

// ---------------- zero deg + pmax ----------------------------------------
__global__ void zero_kernel() {
    int i = blockIdx.x * 256 + threadIdx.x;
    if (i < N_NODES) d_deg[i] = 0;
    if (i < N_PRED * N_GRAPHS * DD) d_pmax[i] = 0u;
}

// ---------------- histogram of dst ---------------------------------------
__global__ void hist_kernel(const int* __restrict__ dst) {
    int e = blockIdx.x * 256 + threadIdx.x;   // 3125 blocks exactly
    atomicAdd(&d_deg[dst[e]], 1);
}

// ------- single-block exclusive scan, thread-coarsened (49 elem/thr) -----
__global__ void scan_kernel() {
    const int C = 49;   // 1024 * 49 = 50176 >= N_NODES
    __shared__ int wsum[32];
    int tid = threadIdx.x, lane = tid & 31, wid = tid >> 5;
    int base = tid * C;
    int s = 0;
    for (int k = 0; k < C; k++) {
        int i = base + k;
        if (i < N_NODES) s += d_deg[i];
    }
    int x = s;
#pragma unroll
    for (int o = 1; o < 32; o <<= 1) {
        int y = __shfl_up_sync(0xffffffffu, x, o);
        if (lane >= o) x += y;
    }
    if (lane == 31) wsum[wid] = x;
    __syncthreads();
    if (wid == 0) {
        int w = wsum[lane];
#pragma unroll
        for (int o = 1; o < 32; o <<= 1) {
            int y = __shfl_up_sync(0xffffffffu, w, o);
            if (lane >= o) w += y;
        }
        wsum[lane] = w;
    }
    __syncthreads();
    int excl = x - s + (wid ? wsum[wid - 1] : 0);
    for (int k = 0; k < C; k++) {
        int i = base + k;
        if (i < N_NODES) {
            int v = d_deg[i];
            d_off[i] = excl;
            d_deg[i] = excl;   // becomes fill cursor
            excl += v;
        }
    }
}

// ---------------- permute edges into CSR ----------------------------------
// after this, d_deg[n] == row end
__global__ void permute_kernel(const int* __restrict__ src,
                               const int* __restrict__ dst) {
    int e = blockIdx.x * 256 + threadIdx.x;   // 3125 blocks exactly
    int d = dst[e];
    int pos = atomicAdd(&d_deg[d], 1);
    d_csr[pos] = src[e];
}

// ------- gather: z[n] = h[n] + sum_{j->n} h[src], unrolled x4 -------------
// 16 threads per node, float4 per thread. Also zeroes BN stats.
__global__ void gather_kernel(const float* __restrict__ x, int layer) {
    if (blockIdx.x == 0 && threadIdx.x < 128) d_stats[threadIdx.x] = 0.f;
    const float* h = layer ? (const float*)d_h : x;
    int t = blockIdx.x * 256 + threadIdx.x;   // 800000 threads exactly
    int node = t >> 4;
    int c = (t & 15) << 2;
    int beg = d_off[node];
    int end = d_deg[node];
    float4 a = *(const float4*)(h + (size_t)node * DD + c);
    float4 a2 = make_float4(0.f, 0.f, 0.f, 0.f);
    int j = beg;
    for (; j + 4 <= end; j += 4) {
        int s0 = __ldg(&d_csr[j + 0]);
        int s1 = __ldg(&d_csr[j + 1]);
        int s2 = __ldg(&d_csr[j + 2]);
        int s3 = __ldg(&d_csr[j + 3]);
        float4 v0 = *(const float4*)(h + (size_t)s0 * DD + c);
        float4 v1 = *(const float4*)(h + (size_t)s1 * DD + c);
        float4 v2 = *(const float4*)(h + (size_t)s2 * DD + c);
        float4 v3 = *(const float4*)(h + (size_t)s3 * DD + c);
        a.x += v0.x; a.y += v0.y; a.z += v0.z; a.w += v0.w;
        a2.x += v1.x; a2.y += v1.y; a2.z += v1.z; a2.w += v1.w;
        a.x += v2.x; a.y += v2.y; a.z += v2.z; a.w += v2.w;
        a2.x += v3.x; a2.y += v3.y; a2.z += v3.z; a2.w += v3.w;
    }
    for (; j < end; j++) {
        int s = __ldg(&d_csr[j]);
        float4 v = *(const float4*)(h + (size_t)s * DD + c);
        a.x += v.x; a.y += v.y; a.z += v.z; a.w += v.w;
    }
    a.x += a2.x; a.y += a2.y; a.z += a2.z; a.w += a2.w;
    *(float4*)(d_z + (size_t)node * DD + c) = a;
}

// ---------------- fused MLP + BN col stats (FFMA2) ------------------------
// BM=128 rows/block, 128 threads, 8x8 register tiles.
__global__ void __launch_bounds__(128) mlp_kernel(
        const float* __restrict__ W1, const float* __restrict__ b1,
        const float* __restrict__ W2, const float* __restrict__ b2) {
    extern __shared__ float smem[];
    float (*zs)[65] = (float(*)[65])smem;                    // [128][65]
    float (*ws)[64] = (float(*)[64])(smem + 128 * 65);       // [64][64]

    int tid = threadIdx.x;
    int rbase = blockIdx.x * 128;

    for (int i = tid; i < 4096; i += 128) ws[i >> 6][i & 63] = W1[i];
    for (int idx = tid; idx < 128 * 16; idx += 128) {
        int r = idx >> 4, c4 = (idx & 15) << 2;
        int gr = rbase + r;
        float4 v = (gr < N_NODES)
                 ? *(const float4*)(d_z + (size_t)gr * DD + c4)
                 : make_float4(0.f, 0.f, 0.f, 0.f);
        zs[r][c4 + 0] = v.x; zs[r][c4 + 1] = v.y;
        zs[r][c4 + 2] = v.z; zs[r][c4 + 3] = v.w;
    }
    __syncthreads();

    int tx = tid & 7, ty = tid >> 3;
    int c0 = tx << 3, r0 = ty << 3;

    unsigned long long acc[8][4];
#pragma unroll
    for (int i = 0; i < 8; i++)
#pragma unroll
        for (int p = 0; p < 4; p++) acc[i][p] = 0ull;

#pragma unroll 4
    for (int k = 0; k < 64; k++) {
        unsigned long long bb[4];
#pragma unroll
        for (int p = 0; p < 4; p++)
            bb[p] = *(const unsigned long long*)&ws[k][c0 + 2 * p];
#pragma unroll
        for (int i = 0; i < 8; i++) {
            unsigned ai = __float_as_uint(zs[r0 + i][k]);
            unsigned long long aa;
            asm("mov.b64 %0, {%1, %1};" : "=l"(aa) : "r"(ai));
#pragma unroll
            for (int p = 0; p < 4; p++)
                asm("fma.rn.f32x2 %0, %1, %2, %0;"
                    : "+l"(acc[i][p]) : "l"(aa), "l"(bb[p]));
        }
    }
    __syncthreads();

    // bias + relu -> back into zs; load W2
#pragma unroll
    for (int i = 0; i < 8; i++) {
#pragma unroll
        for (int p = 0; p < 4; p++) {
            unsigned ulo, uhi;
            asm("mov.b64 {%0, %1}, %2;" : "=r"(ulo), "=r"(uhi) : "l"(acc[i][p]));
            float lo = __uint_as_float(ulo) + __ldg(&b1[c0 + 2 * p]);
            float hi = __uint_as_float(uhi) + __ldg(&b1[c0 + 2 * p + 1]);
            zs[r0 + i][c0 + 2 * p] = lo > 0.f ? lo : 0.f;
            zs[r0 + i][c0 + 2 * p + 1] = hi > 0.f ? hi : 0.f;
        }
    }
    for (int i = tid; i < 4096; i += 128) ws[i >> 6][i & 63] = W2[i];
    __syncthreads();

#pragma unroll
    for (int i = 0; i < 8; i++)
#pragma unroll
        for (int p = 0; p < 4; p++) acc[i][p] = 0ull;

#pragma unroll 4
    for (int k = 0; k < 64; k++) {
        unsigned long long bb[4];
#pragma unroll
        for (int p = 0; p < 4; p++)
            bb[p] = *(const unsigned long long*)&ws[k][c0 + 2 * p];
#pragma unroll
        for (int i = 0; i < 8; i++) {
            unsigned ai = __float_as_uint(zs[r0 + i][k]);
            unsigned long long aa;
            asm("mov.b64 %0, {%1, %1};" : "=l"(aa) : "r"(ai));
#pragma unroll
            for (int p = 0; p < 4; p++)
                asm("fma.rn.f32x2 %0, %1, %2, %0;"
                    : "+l"(acc[i][p]) : "l"(aa), "l"(bb[p]));
        }
    }

    // bias, write y, per-column stats
    float psum[8], psq[8];
#pragma unroll
    for (int j = 0; j < 8; j++) { psum[j] = 0.f; psq[j] = 0.f; }
    float bb2[8];
#pragma unroll
    for (int j = 0; j < 8; j++) bb2[j] = __ldg(&b2[c0 + j]);
#pragma unroll
    for (int i = 0; i < 8; i++) {
        int gr = rbase + r0 + i;
        if (gr < N_NODES) {
            float o[8];
#pragma unroll
            for (int p = 0; p < 4; p++) {
                unsigned ulo, uhi;
                asm("mov.b64 {%0, %1}, %2;" : "=r"(ulo), "=r"(uhi) : "l"(acc[i][p]));
                o[2 * p] = __uint_as_float(ulo) + bb2[2 * p];
                o[2 * p + 1] = __uint_as_float(uhi) + bb2[2 * p + 1];
            }
            float4* yo = (float4*)(d_y + (size_t)gr * DD + c0);
            yo[0] = make_float4(o[0], o[1], o[2], o[3]);
            yo[1] = make_float4(o[4], o[5], o[6], o[7]);
#pragma unroll
            for (int j = 0; j < 8; j++) {
                psum[j] += o[j];
                psq[j] += o[j] * o[j];
            }
        }
    }
    // reduce across the 4 row-groups within each warp (lane bits 3,4)
#pragma unroll
    for (int j = 0; j < 8; j++) {
        psum[j] += __shfl_xor_sync(0xffffffffu, psum[j], 8);
        psum[j] += __shfl_xor_sync(0xffffffffu, psum[j], 16);
        psq[j]  += __shfl_xor_sync(0xffffffffu, psq[j], 8);
        psq[j]  += __shfl_xor_sync(0xffffffffu, psq[j], 16);
    }
    if ((tid & 31) < 8) {
#pragma unroll
        for (int j = 0; j < 8; j++) {
            atomicAdd(&d_stats[c0 + j], psum[j]);
            atomicAdd(&d_stats[64 + c0 + j], psq[j]);
        }
    }
}

// ---------------- max-pool of raw input (slot 0), 1024 blocks -------------
__global__ void pool_x_kernel(const float* __restrict__ in) {
    int g = blockIdx.x >> 4, chunk = blockIdx.x & 15;
    int tid = threadIdx.x;
    int gs = (int)(((long long)g * N_NODES + 63) >> 6);
    int ge = (int)(((long long)(g + 1) * N_NODES + 63) >> 6);
    int cnt = ge - gs;
    int step = (cnt + 15) >> 4;
    int cs = gs + chunk * step;
    int ce = min(cs + step, ge);
    int col = tid & 63, rs = tid >> 6;
    float m = -3.402823466e+38f;
    for (int r = cs + rs; r < ce; r += 4)
        m = fmaxf(m, __ldg(in + (size_t)r * DD + col));
    __shared__ float red[256];
    red[tid] = m;
    __syncthreads();
    if (rs == 0 && cs < ce) {
        m = fmaxf(fmaxf(red[col], red[64 + col]),
                  fmaxf(red[128 + col], red[192 + col]));
        atomicMax(&d_pmax[g * DD + col], enc_f(m));
    }
}

// ------- BN finalize + PReLU + write h + max-pool, 1024 blocks ------------
__global__ void normpool_kernel(const float* __restrict__ gamma,
                                const float* __restrict__ beta,
                                const float* __restrict__ alpha_p, int slot) {
    int g = blockIdx.x >> 4, chunk = blockIdx.x & 15;
    int tid = threadIdx.x;
    int col = tid & 63, rs = tid >> 6;
    float mean = d_stats[col] * (1.f / N_NODES);
    float msq = d_stats[64 + col] * (1.f / N_NODES);
    float var = msq - mean * mean;
    float rstd = rsqrtf(var + 1e-5f);
    float scale = rstd * __ldg(&gamma[col]);
    float bias = __ldg(&beta[col]) - mean * scale;
    float al = __ldg(alpha_p);

    int gs = (int)(((long long)g * N_NODES + 63) >> 6);
    int ge = (int)(((long long)(g + 1) * N_NODES + 63) >> 6);
    int cnt = ge - gs;
    int step = (cnt + 15) >> 4;
    int cs = gs + chunk * step;
    int ce = min(cs + step, ge);

    float m = -3.402823466e+38f;
    for (int r = cs + rs; r < ce; r += 4) {
        float v = d_y[(size_t)r * DD + col] * scale + bias;
        v = v > 0.f ? v : al * v;
        d_h[(size_t)r * DD + col] = v;
        m = fmaxf(m, v);
    }
    __shared__ float red[256];
    red[tid] = m;
    __syncthreads();
    if (rs == 0 && cs < ce) {
        m = fmaxf(fmaxf(red[col], red[64 + col]),
                  fmaxf(red[128 + col], red[192 + col]));
        atomicMax(&d_pmax[slot * (N_GRAPHS * DD) + g * DD + col], enc_f(m));
    }
}

// ---------------- prediction heads: out[g, d*5 + l] -----------------------
__global__ void head_kernel(const float* __restrict__ pW,
                            const float* __restrict__ pb,
                            float* __restrict__ out) {
    int g = blockIdx.x, tid = threadIdx.x;   // 320 threads
    __shared__ float ps[N_PRED * DD];
    ps[tid] = dec_f(d_pmax[(tid >> 6) * (N_GRAPHS * DD) + g * DD + (tid & 63)]);
    __syncthreads();
    int l = tid >> 6, dd = tid & 63;
    float acc = __ldg(&pb[l * DD + dd]);
    const float* w = pW + l * DD * DD + dd;
    const float* p = ps + l * DD;
#pragma unroll 16
    for (int k = 0; k < DD; k++) acc += p[k] * __ldg(&w[k * DD]);
    out[g * (N_PRED * DD) + dd * N_PRED + l] = acc;
}

// ---------------- launch --------------------------------------------------
extern "C" void kernel_launch(void* const* d_in, const int* in_sizes, int n_in,
                              void* d_out, int out_size) {
    const float* x     = (const float*)d_in[0];
    const int* ei      = (const int*)d_in[1];
    // d_in[2] = batch (contiguous; recomputed analytically)
    const float* W1    = (const float*)d_in[3];
    const float* b1    = (const float*)d_in[4];
    const float* W2    = (const float*)d_in[5];
    const float* b2    = (const float*)d_in[6];
    const float* gamma = (const float*)d_in[7];
    const float* beta  = (const float*)d_in[8];
    const float* alpha = (const float*)d_in[9];
    const float* pW    = (const float*)d_in[10];
    const float* pb    = (const float*)d_in[11];
    float* out = (float*)d_out;

    const int* src = ei;
    const int* dst = ei + N_EDGES;

    const int MLP_SMEM = (128 * 65 + 64 * 64) * 4;  // 49664 bytes
    cudaFuncSetAttribute(mlp_kernel,
                         cudaFuncAttributeMaxDynamicSharedMemorySize, MLP_SMEM);

    zero_kernel<<<(N_NODES + 255) / 256, 256>>>();
    hist_kernel<<<N_EDGES / 256, 256>>>(dst);
    scan_kernel<<<1, 1024>>>();
    permute_kernel<<<N_EDGES / 256, 256>>>(src, dst);

    pool_x_kernel<<<N_GRAPHS * 16, 256>>>(x);

    for (int l = 0; l < N_GIN; l++) {
        gather_kernel<<<(N_NODES * 16) / 256, 256>>>(x, l);
        mlp_kernel<<<(N_NODES + 127) / 128, 128, MLP_SMEM>>>(
            W1 + l * 4096, b1 + l * 64, W2 + l * 4096, b2 + l * 64);
        normpool_kernel<<<N_GRAPHS * 16, 256>>>(gamma + l * 64, beta + l * 64,
                                                alpha, l + 1);
    }

    head_kernel<<<N_GRAPHS, 320>>>(pW, pb, out);
}